// round 13
// baseline (speedup 1.0000x reference)
#include <cuda_runtime.h>
#include <cuda_fp16.h>
#include <cstdint>

// ============================================================
// Problem constants
// ============================================================
#define N_TOK  262144
#define DDIM   256
#define HDIM   256
#define NEXP   8
#define NPAIR  28

// ============================================================
// Device scratch (allocation-free contract: __device__ globals)
// ============================================================
__device__ unsigned g_pcnt[NPAIR];
__device__ unsigned g_ptok[NPAIR][N_TOK];   // token id per routed row
__device__ float    g_pgp [NPAIR][N_TOK];   // gate of lower-index expert p
__device__ float    g_pgq [NPAIR][N_TOK];   // gate of higher-index expert q
__device__ __half   g_xh[(size_t)N_TOK * DDIM];      // x in fp16
__device__ __half   g_wh[NEXP * HDIM * DDIM];        // W in fp16

// pair id -> expert indices
__device__ const int c_pair_p[NPAIR] =
    {0,0,0,0,0,0,0, 1,1,1,1,1,1, 2,2,2,2,2, 3,3,3,3, 4,4,4, 5,5, 6};
__device__ const int c_pair_q[NPAIR] =
    {1,2,3,4,5,6,7, 2,3,4,5,6,7, 3,4,5,6,7, 4,5,6,7, 5,6,7, 6,7, 7};

// ============================================================
// PTX helpers (plain sm_100 ONLY: cp.async, ldmatrix, mma.sync)
// ============================================================
__device__ __forceinline__ uint32_t smem_u32(const void* p) {
    uint32_t a;
    asm("{ .reg .u64 t; cvta.to.shared.u64 t, %1; cvt.u32.u64 %0, t; }" : "=r"(a) : "l"(p));
    return a;
}

#define CP_ASYNC16(dst, src) \
    asm volatile("cp.async.cg.shared.global [%0], [%1], 16;" :: "r"(dst), "l"(src))
#define CP_COMMIT() asm volatile("cp.async.commit_group;" ::: "memory")
#define CP_WAIT(n)  asm volatile("cp.async.wait_group %0;" :: "n"(n) : "memory")

__device__ __forceinline__ void ldsm4(uint32_t addr, uint32_t* r) {
    asm volatile("ldmatrix.sync.aligned.m8n8.x4.shared.b16 {%0,%1,%2,%3}, [%4];"
                 : "=r"(r[0]), "=r"(r[1]), "=r"(r[2]), "=r"(r[3]) : "r"(addr));
}

__device__ __forceinline__ void mma16816(float* c, const uint32_t* a,
                                         uint32_t b0, uint32_t b1) {
    asm volatile(
        "mma.sync.aligned.m16n8k16.row.col.f32.f16.f16.f32 "
        "{%0,%1,%2,%3}, {%4,%5,%6,%7}, {%8,%9}, {%0,%1,%2,%3};"
        : "+f"(c[0]), "+f"(c[1]), "+f"(c[2]), "+f"(c[3])
        : "r"(a[0]), "r"(a[1]), "r"(a[2]), "r"(a[3]), "r"(b0), "r"(b1));
}

// ============================================================
// Kernel 0: reset routing counters (graph-replay safe)
// ============================================================
__global__ void reset_kernel() {
    if (threadIdx.x < NPAIR) g_pcnt[threadIdx.x] = 0u;
}

// ============================================================
// Kernel 1: expert weights fp32 -> fp16
// ============================================================
__global__ void convert_w_kernel(const float* __restrict__ ew) {
    int i = blockIdx.x * 256 + threadIdx.x;           // pair index, total E*H*D/2
    float2 v = ((const float2*)ew)[i];
    __half2 h;
    h.x = __float2half_rn(v.x);
    h.y = __float2half_rn(v.y);
    ((__half2*)g_wh)[i] = h;
}

// ============================================================
// Kernel 2: gate + softmax + top-2 + pair routing + x -> fp16
//   one warp per token, 8 warps per block
//   (expert, segment) lane mapping: lane = 4e+seg; lane computes the
//   full partial dot of expert e over cols [64*seg, 64*seg+64) from
//   smem-staged x and a PERMUTED gw layout. Reductions: 2 shuffles
//   (vs 8x5 before); logits regathered with 8 broadcast shuffles.
// ============================================================
__global__ __launch_bounds__(256) void gate_route_kernel(
    const float* __restrict__ x,
    const float* __restrict__ gw,
    const float* __restrict__ gb)
{
    // permuted gw: sgw4[i*32 + lane] = gw[lane>>2][(lane&3)*64 + 4i .. +3]
    __shared__ float4 sgw4[512];          // 8 KB
    __shared__ float  sgb[NEXP];
    __shared__ float4 sxv[8][68];         // per warp, [seg*17 + i], padded
    {
        const float4* gw4g = (const float4*)gw;
        for (int idx = threadIdx.x; idx < 512; idx += 256) {
            int i = idx >> 5, ln = idx & 31;
            sgw4[idx] = gw4g[(ln >> 2) * 64 + (ln & 3) * 16 + i];
        }
        if (threadIdx.x < NEXP) sgb[threadIdx.x] = gb[threadIdx.x];
    }
    __syncthreads();

    int warp = threadIdx.x >> 5, lane = threadIdx.x & 31;
    int t = blockIdx.x * 8 + warp;

    // coalesced x load: lane owns cols [4*lane,4*lane+4) and +128
    const float4* xrow4 = (const float4*)(x + (size_t)t * DDIM);
    float4 xv[2];
#pragma unroll
    for (int j = 0; j < 2; j++) xv[j] = xrow4[j * 32 + lane];

    // x -> fp16 (uint2 = 4 halves per store, coalesced)
    uint2* xh4 = (uint2*)(g_xh + (size_t)t * DDIM);
#pragma unroll
    for (int j = 0; j < 2; j++) {
        __half2 lo2, hi2;
        lo2.x = __float2half_rn(xv[j].x);
        lo2.y = __float2half_rn(xv[j].y);
        hi2.x = __float2half_rn(xv[j].z);
        hi2.y = __float2half_rn(xv[j].w);
        uint2 u;
        u.x = *(uint32_t*)&lo2;
        u.y = *(uint32_t*)&hi2;
        xh4[j * 32 + lane] = u;
    }

    // stage x into padded smem: cols 128j+4*lane -> [seg= 2j+(lane>>4)][i= lane&15]
#pragma unroll
    for (int j = 0; j < 2; j++) {
        int seg = 2 * j + (lane >> 4);
        int i   = lane & 15;
        sxv[warp][seg * 17 + i] = xv[j];
    }
    __syncwarp();

    // lane (e=lane>>2, seg=lane&3): partial dot over its 64-col slice
    int eL = lane >> 2, segL = lane & 3;
    float a = 0.f;
#pragma unroll
    for (int i = 0; i < 16; i++) {
        float4 xw = sxv[warp][segL * 17 + i];
        float4 w  = sgw4[i * 32 + lane];
        a += xw.x * w.x + xw.y * w.y + xw.z * w.z + xw.w * w.w;
    }
    // reduce across the 4 seg-lanes of each expert (2 levels)
    a += __shfl_xor_sync(0xffffffffu, a, 1);
    a += __shfl_xor_sync(0xffffffffu, a, 2);
    float la = a + sgb[eL];

    // regather all 8 logits into every lane
    float logit[NEXP];
#pragma unroll
    for (int e = 0; e < NEXP; e++)
        logit[e] = __shfl_sync(0xffffffffu, la, e * 4);

    // top-2 by logit (monotone with softmax prob; ties -> lowest index)
    int i0 = 0; float b0 = logit[0];
#pragma unroll
    for (int e = 1; e < NEXP; e++) if (logit[e] > b0) { b0 = logit[e]; i0 = e; }
    int i1 = -1; float b1 = -3.4e38f;
#pragma unroll
    for (int e = 0; e < NEXP; e++) if (e != i0 && logit[e] > b1) { b1 = logit[e]; i1 = e; }

    // softmax values for the two winners
    float s = 0.f;
#pragma unroll
    for (int e = 0; e < NEXP; e++) s += expf(logit[e] - b0);
    float inv = 1.f / s;
    float gv0 = expf(logit[i0] - b0) * inv;
    float gv1 = expf(logit[i1] - b0) * inv;

    if (lane == 0) {
        int p = min(i0, i1), q = max(i0, i1);
        float gp = (p == i0) ? gv0 : gv1;
        float gq = (p == i0) ? gv1 : gv0;
        int pid = p * 7 - (p * (p - 1)) / 2 + (q - p - 1);
        unsigned pos = atomicAdd(&g_pcnt[pid], 1u);
        g_ptok[pid][pos] = (unsigned)t;
        g_pgp [pid][pos] = gp;
        g_pgq [pid][pos] = gq;
    }
}

// ============================================================
// Kernel 3: pair-fused routed GEMM, single-term fp16 mma.sync
//   block = 128 tokens x ONE 128-col H-half of expert pair (p,q)
//   A (128x256 fp16 = 64 KB) is RESIDENT in smem, loaded once;
//   only B streams through a 2-stage pipeline (2 x 16 KB).
//   8 B-chunks (BK=64): 0-3 sweep W_p, 4-7 sweep W_q; accumulators
//   rescaled by g_p/g_q between sweeps; epilogue writes direct to out.
//   8 warps (256 thr) in 4(M)x2(N), warp tile 32x64, 2 CTAs/SM.
// ============================================================
static constexpr int OFF_TOK  = 0;      // 128 u32
static constexpr int OFF_GP   = 512;    // 128 f32
static constexpr int OFF_GQ   = 1024;   // 128 f32
static constexpr int OFF_BP   = 1536;   // 128 f32 (this half)
static constexpr int OFF_BQ   = 2048;   // 128 f32 (this half)
static constexpr int OFF_A    = 4096;   // 4 kslices x 16KB = 64 KB resident
static constexpr int OFF_B    = 69632;  // 2 bufs x 16KB
static constexpr int SMEM_TOTAL = 102400;
#define GEMM_THREADS 256
#define MAX_TILES 256                    // 256*128 = 32768 tokens/pair cap

__device__ __forceinline__ void load_A_all(uint32_t sbase, const unsigned* s_tok)
{
    int tid = threadIdx.x;
    uint32_t a_s = sbase + OFF_A;
    // 128 rows x 256B (4 kslices x 128B) = 4096 16B units
#pragma unroll
    for (int i = 0; i < 16; i++) {
        int u = tid + i * GEMM_THREADS;
        int ks = u >> 10;
        int rem = u & 1023;
        int r = rem >> 3, q8 = rem & 7;
        unsigned tok = s_tok[r];
        size_t g = (size_t)tok * DDIM + ks * 64 + q8 * 8;
        uint32_t d = a_s + (uint32_t)(ks * 16384 + r * 128 + ((q8 ^ (r & 7)) << 4));
        CP_ASYNC16(d, g_xh + g);
    }
}

__device__ __forceinline__ void load_B(uint32_t sbase, int buf, int kslice,
                                       int e, int nhalf)
{
    int tid = threadIdx.x;
    uint32_t b_s = sbase + OFF_B + buf * 16384;
    // B: 128 rows (this H-half) x 128B = 1024 16B units
#pragma unroll
    for (int i = 0; i < 4; i++) {
        int u = tid + i * GEMM_THREADS;
        int h = u >> 3, q8 = u & 7;
        size_t g = (size_t)e * (HDIM * DDIM) + (size_t)(nhalf * 128 + h) * DDIM
                 + kslice * 64 + q8 * 8;
        uint32_t d = b_s + (uint32_t)(h * 128 + ((q8 ^ (h & 7)) << 4));
        CP_ASYNC16(d, g_wh + g);
    }
}

__global__ __launch_bounds__(GEMM_THREADS, 2) void moe_gemm_kernel(
    const float* __restrict__ eb, float* __restrict__ out)
{
    int pid = blockIdx.y;
    int nhalf = blockIdx.x & 1;
    unsigned tile = blockIdx.x >> 1;
    unsigned cnt = g_pcnt[pid];
    unsigned row0 = tile * 128u;
    if (row0 >= cnt) return;
    int rows = (int)min(128u, cnt - row0);
    int ep = c_pair_p[pid], eq = c_pair_q[pid];

    extern __shared__ char smem[];
    uint32_t sbase = smem_u32(smem);
    unsigned* s_tok = (unsigned*)(smem + OFF_TOK);
    float*    s_gp  = (float*)(smem + OFF_GP);
    float*    s_gq  = (float*)(smem + OFF_GQ);
    float*    s_bp  = (float*)(smem + OFF_BP);
    float*    s_bq  = (float*)(smem + OFF_BQ);

    int tid = threadIdx.x, wid = tid >> 5, lane = tid & 31;

    if (tid < 128) {
        bool v = (tid < rows);
        s_tok[tid] = v ? g_ptok[pid][row0 + tid] : 0u;
        s_gp [tid] = v ? g_pgp[pid][row0 + tid] : 0.f;
        s_gq [tid] = v ? g_pgq[pid][row0 + tid] : 1.f;   // keep ratio finite
    } else {
        int c0 = tid - 128;          // 0..127: bias for this H-half
        s_bp[c0] = eb[ep * HDIM + nhalf * 128 + c0];
        s_bq[c0] = eb[eq * HDIM + nhalf * 128 + c0];
    }
    __syncthreads();

    // A resident (one shot) + 2-stage B pipeline
    load_A_all(sbase, s_tok);
    load_B(sbase, 0, 0, ep, nhalf); CP_COMMIT();   // G0 = A + B0
    load_B(sbase, 1, 1, ep, nhalf); CP_COMMIT();   // G1 = B1

    // warp tile: 4 (M) x 2 (N) -> 32 rows x 64 cols per warp
    int warp_m = wid & 3;
    int warp_n = wid >> 2;

    // ldmatrix lane address components (PTX fragment layouts)
    int laneA_row = (lane & 7) + (((lane >> 3) & 1) << 3);
    int laneA_q   = (lane >> 4) & 1;
    int laneB_n   = (lane & 7) + (((lane >> 4) & 1) << 3);
    int laneB_q   = (lane >> 3) & 1;
    int grp = lane >> 2, tig = lane & 3;

    float acc[2][8][4];
#pragma unroll
    for (int a = 0; a < 2; a++)
#pragma unroll
        for (int b = 0; b < 8; b++)
#pragma unroll
            for (int d = 0; d < 4; d++) acc[a][b][d] = 0.f;

#pragma unroll 1
    for (int c = 0; c < 8; c++) {
        int buf = c & 1;
        if (c == 7) { CP_WAIT(0); } else { CP_WAIT(1); }
        __syncthreads();

        uint32_t aBase = sbase + OFF_A + (c & 3) * 16384;
        uint32_t bBase = sbase + OFF_B + buf * 16384;

#pragma unroll
        for (int ks = 0; ks < 4; ks++) {
            uint32_t ahf[2][4];
#pragma unroll
            for (int mf = 0; mf < 2; mf++) {
                int r = warp_m * 32 + mf * 16 + laneA_row;
                int q8 = ks * 2 + laneA_q;
                uint32_t off = (uint32_t)(r * 128 + ((q8 ^ (r & 7)) << 4));
                ldsm4(aBase + off, ahf[mf]);
            }
#pragma unroll
            for (int nf = 0; nf < 4; nf++) {
                int n = warp_n * 64 + nf * 16 + laneB_n;
                int q8 = ks * 2 + laneB_q;
                uint32_t off = (uint32_t)(n * 128 + ((q8 ^ (n & 7)) << 4));
                uint32_t bh[4];
                ldsm4(bBase + off, bh);
#pragma unroll
                for (int mf = 0; mf < 2; mf++) {
                    mma16816(acc[mf][2 * nf],     ahf[mf], bh[0], bh[1]);
                    mma16816(acc[mf][2 * nf + 1], ahf[mf], bh[2], bh[3]);
                }
            }
        }

        // Between the two expert sweeps: acc *= g_p/g_q per row
        if (c == 3) {
#pragma unroll
            for (int mf = 0; mf < 2; mf++) {
#pragma unroll
                for (int half = 0; half < 2; half++) {
                    int r = warp_m * 32 + mf * 16 + grp + half * 8;
                    float f = s_gp[r] / s_gq[r];
#pragma unroll
                    for (int nf = 0; nf < 8; nf++) {
                        acc[mf][nf][half * 2 + 0] *= f;
                        acc[mf][nf][half * 2 + 1] *= f;
                    }
                }
            }
        }

        __syncthreads();
        if (c < 6) {
            int nc = c + 2;
            load_B(sbase, buf, nc & 3, (nc < 4) ? ep : eq, nhalf);
            CP_COMMIT();
        }
    }

    // Epilogue: out[tok, nhalf-half] = g_q*acc + g_p*b_p + g_q*b_q
#pragma unroll
    for (int mf = 0; mf < 2; mf++) {
#pragma unroll
        for (int half = 0; half < 2; half++) {
            int r = warp_m * 32 + mf * 16 + grp + half * 8;
            if (r < rows) {
                unsigned tok = s_tok[r];
                float gq = s_gq[r], gp = s_gp[r];
                float* dst = out + (size_t)tok * HDIM + nhalf * 128;
#pragma unroll
                for (int nf = 0; nf < 8; nf++) {
                    int col = warp_n * 64 + nf * 8 + tig * 2;
                    float2 v;
                    v.x = gq * acc[mf][nf][half * 2 + 0] + gp * s_bp[col]     + gq * s_bq[col];
                    v.y = gq * acc[mf][nf][half * 2 + 1] + gp * s_bp[col + 1] + gq * s_bq[col + 1];
                    *(float2*)(dst + col) = v;
                }
            }
        }
    }
}

// ============================================================
// Launch
// ============================================================
extern "C" void kernel_launch(void* const* d_in, const int* in_sizes, int n_in,
                              void* d_out, int out_size)
{
    const float* x  = (const float*)d_in[0];
    const float* gw = (const float*)d_in[1];
    const float* gb = (const float*)d_in[2];
    const float* ew = (const float*)d_in[3];
    const float* eb = (const float*)d_in[4];
    float* out = (float*)d_out;

    cudaFuncSetAttribute(moe_gemm_kernel,
                         cudaFuncAttributeMaxDynamicSharedMemorySize, SMEM_TOTAL);

    reset_kernel<<<1, 32>>>();
    convert_w_kernel<<<(NEXP * HDIM * DDIM / 2) / 256, 256>>>(ew);
    gate_route_kernel<<<N_TOK / 8, 256>>>(x, gw, gb);
    moe_gemm_kernel<<<dim3(MAX_TILES * 2, NPAIR), GEMM_THREADS, SMEM_TOTAL>>>(eb, out);
}

// round 14
// speedup vs baseline: 1.0835x; 1.0835x over previous
#include <cuda_runtime.h>
#include <cuda_fp16.h>
#include <cstdint>

// ============================================================
// Problem constants
// ============================================================
#define N_TOK  262144
#define DDIM   256
#define HDIM   256
#define NEXP   8
#define NPAIR  28

// ============================================================
// Device scratch (allocation-free contract: __device__ globals)
// ============================================================
__device__ unsigned g_pcnt[NPAIR];
__device__ unsigned g_ptok[NPAIR][N_TOK];   // token id per routed row
__device__ float    g_pgp [NPAIR][N_TOK];   // gate of lower-index expert p
__device__ float    g_pgq [NPAIR][N_TOK];   // gate of higher-index expert q
__device__ __half   g_xh[(size_t)N_TOK * DDIM];      // x in fp16
__device__ __half   g_wh[NEXP * HDIM * DDIM];        // W in fp16

// pair id -> expert indices
__device__ const int c_pair_p[NPAIR] =
    {0,0,0,0,0,0,0, 1,1,1,1,1,1, 2,2,2,2,2, 3,3,3,3, 4,4,4, 5,5, 6};
__device__ const int c_pair_q[NPAIR] =
    {1,2,3,4,5,6,7, 2,3,4,5,6,7, 3,4,5,6,7, 4,5,6,7, 5,6,7, 6,7, 7};

// ============================================================
// PTX helpers (plain sm_100 ONLY: cp.async, ldmatrix, mma.sync)
// ============================================================
__device__ __forceinline__ uint32_t smem_u32(const void* p) {
    uint32_t a;
    asm("{ .reg .u64 t; cvta.to.shared.u64 t, %1; cvt.u32.u64 %0, t; }" : "=r"(a) : "l"(p));
    return a;
}

#define CP_ASYNC16(dst, src) \
    asm volatile("cp.async.cg.shared.global [%0], [%1], 16;" :: "r"(dst), "l"(src))
#define CP_COMMIT() asm volatile("cp.async.commit_group;" ::: "memory")
#define CP_WAIT(n)  asm volatile("cp.async.wait_group %0;" :: "n"(n) : "memory")

__device__ __forceinline__ void ldsm4(uint32_t addr, uint32_t* r) {
    asm volatile("ldmatrix.sync.aligned.m8n8.x4.shared.b16 {%0,%1,%2,%3}, [%4];"
                 : "=r"(r[0]), "=r"(r[1]), "=r"(r[2]), "=r"(r[3]) : "r"(addr));
}

__device__ __forceinline__ void mma16816(float* c, const uint32_t* a,
                                         uint32_t b0, uint32_t b1) {
    asm volatile(
        "mma.sync.aligned.m16n8k16.row.col.f32.f16.f16.f32 "
        "{%0,%1,%2,%3}, {%4,%5,%6,%7}, {%8,%9}, {%0,%1,%2,%3};"
        : "+f"(c[0]), "+f"(c[1]), "+f"(c[2]), "+f"(c[3])
        : "r"(a[0]), "r"(a[1]), "r"(a[2]), "r"(a[3]), "r"(b0), "r"(b1));
}

// ============================================================
// Kernel 0: reset routing counters (graph-replay safe)
// ============================================================
__global__ void reset_kernel() {
    if (threadIdx.x < NPAIR) g_pcnt[threadIdx.x] = 0u;
}

// ============================================================
// Kernel 1: expert weights fp32 -> fp16
// ============================================================
__global__ void convert_w_kernel(const float* __restrict__ ew) {
    int i = blockIdx.x * 256 + threadIdx.x;           // pair index, total E*H*D/2
    float2 v = ((const float2*)ew)[i];
    __half2 h;
    h.x = __float2half_rn(v.x);
    h.y = __float2half_rn(v.y);
    ((__half2*)g_wh)[i] = h;
}

// ============================================================
// Kernel 2: gate + softmax + top-2 + pair routing + x -> fp16
//   one warp per token, 8 warps per block  (R12 version — measured)
//   lane owns x[lane*4 .. lane*4+3] and x[128+lane*4 ..] (two float4s)
// ============================================================
__global__ __launch_bounds__(256) void gate_route_kernel(
    const float* __restrict__ x,
    const float* __restrict__ gw,
    const float* __restrict__ gb)
{
    __shared__ float sgw[NEXP * DDIM];   // 8KB, 16B-aligned
    __shared__ float sgb[NEXP];
    for (int i = threadIdx.x; i < NEXP * DDIM; i += 256) sgw[i] = gw[i];
    if (threadIdx.x < NEXP) sgb[threadIdx.x] = gb[threadIdx.x];
    __syncthreads();
    const float4* sgw4 = (const float4*)sgw;

    int warp = threadIdx.x >> 5, lane = threadIdx.x & 31;
    int t = blockIdx.x * 8 + warp;

    // two contiguous float4 per lane: cols [lane*4, lane*4+4) and +128
    const float4* xrow4 = (const float4*)(x + (size_t)t * DDIM);
    float4 xv[2];
#pragma unroll
    for (int j = 0; j < 2; j++) xv[j] = xrow4[j * 32 + lane];

    // x -> fp16 (uint2 = 4 halves per store, coalesced)
    uint2* xh4 = (uint2*)(g_xh + (size_t)t * DDIM);
#pragma unroll
    for (int j = 0; j < 2; j++) {
        __half2 lo2, hi2;
        lo2.x = __float2half_rn(xv[j].x);
        lo2.y = __float2half_rn(xv[j].y);
        hi2.x = __float2half_rn(xv[j].z);
        hi2.y = __float2half_rn(xv[j].w);
        uint2 u;
        u.x = *(uint32_t*)&lo2;
        u.y = *(uint32_t*)&hi2;
        xh4[j * 32 + lane] = u;
    }

    // logits (fp32): per expert, 2 LDS.128 of gw + 8 FMA, then 5-level shuffle
    float logit[NEXP];
#pragma unroll
    for (int e = 0; e < NEXP; e++) {
        float a = 0.f;
#pragma unroll
        for (int j = 0; j < 2; j++) {
            float4 w = sgw4[e * 64 + j * 32 + lane];
            a += xv[j].x * w.x + xv[j].y * w.y + xv[j].z * w.z + xv[j].w * w.w;
        }
#pragma unroll
        for (int o = 16; o; o >>= 1) a += __shfl_xor_sync(0xffffffffu, a, o);
        logit[e] = a + sgb[e];
    }

    // top-2 by logit (monotone with softmax prob; ties -> lowest index)
    int i0 = 0; float b0 = logit[0];
#pragma unroll
    for (int e = 1; e < NEXP; e++) if (logit[e] > b0) { b0 = logit[e]; i0 = e; }
    int i1 = -1; float b1 = -3.4e38f;
#pragma unroll
    for (int e = 0; e < NEXP; e++) if (e != i0 && logit[e] > b1) { b1 = logit[e]; i1 = e; }

    // softmax values for the two winners
    float s = 0.f;
#pragma unroll
    for (int e = 0; e < NEXP; e++) s += expf(logit[e] - b0);
    float inv = 1.f / s;
    float gv0 = expf(logit[i0] - b0) * inv;
    float gv1 = expf(logit[i1] - b0) * inv;

    if (lane == 0) {
        int p = min(i0, i1), q = max(i0, i1);
        float gp = (p == i0) ? gv0 : gv1;
        float gq = (p == i0) ? gv1 : gv0;
        int pid = p * 7 - (p * (p - 1)) / 2 + (q - p - 1);
        unsigned pos = atomicAdd(&g_pcnt[pid], 1u);
        g_ptok[pid][pos] = (unsigned)t;
        g_pgp [pid][pos] = gp;
        g_pgq [pid][pos] = gq;
    }
}

// ============================================================
// Kernel 3: pair-fused routed GEMM, single-term fp16 mma.sync
//   (R13 version — measured 250.2us)
//   block = 128 tokens x ONE 128-col H-half of expert pair (p,q)
//   A (128x256 fp16 = 64 KB) is RESIDENT in smem, loaded once;
//   only B streams through a 2-stage pipeline (2 x 16 KB).
//   8 B-chunks (BK=64): 0-3 sweep W_p, 4-7 sweep W_q; accumulators
//   rescaled by g_p/g_q between sweeps; epilogue writes direct to out.
//   8 warps (256 thr) in 4(M)x2(N), warp tile 32x64, 2 CTAs/SM.
// ============================================================
static constexpr int OFF_TOK  = 0;      // 128 u32
static constexpr int OFF_GP   = 512;    // 128 f32
static constexpr int OFF_GQ   = 1024;   // 128 f32
static constexpr int OFF_BP   = 1536;   // 128 f32 (this half)
static constexpr int OFF_BQ   = 2048;   // 128 f32 (this half)
static constexpr int OFF_A    = 4096;   // 4 kslices x 16KB = 64 KB resident
static constexpr int OFF_B    = 69632;  // 2 bufs x 16KB
static constexpr int SMEM_TOTAL = 102400;
#define GEMM_THREADS 256
#define MAX_TILES 256                    // 256*128 = 32768 tokens/pair cap

__device__ __forceinline__ void load_A_all(uint32_t sbase, const unsigned* s_tok)
{
    int tid = threadIdx.x;
    uint32_t a_s = sbase + OFF_A;
    // 128 rows x 256B (4 kslices x 128B) = 4096 16B units
#pragma unroll
    for (int i = 0; i < 16; i++) {
        int u = tid + i * GEMM_THREADS;
        int ks = u >> 10;
        int rem = u & 1023;
        int r = rem >> 3, q8 = rem & 7;
        unsigned tok = s_tok[r];
        size_t g = (size_t)tok * DDIM + ks * 64 + q8 * 8;
        uint32_t d = a_s + (uint32_t)(ks * 16384 + r * 128 + ((q8 ^ (r & 7)) << 4));
        CP_ASYNC16(d, g_xh + g);
    }
}

__device__ __forceinline__ void load_B(uint32_t sbase, int buf, int kslice,
                                       int e, int nhalf)
{
    int tid = threadIdx.x;
    uint32_t b_s = sbase + OFF_B + buf * 16384;
    // B: 128 rows (this H-half) x 128B = 1024 16B units
#pragma unroll
    for (int i = 0; i < 4; i++) {
        int u = tid + i * GEMM_THREADS;
        int h = u >> 3, q8 = u & 7;
        size_t g = (size_t)e * (HDIM * DDIM) + (size_t)(nhalf * 128 + h) * DDIM
                 + kslice * 64 + q8 * 8;
        uint32_t d = b_s + (uint32_t)(h * 128 + ((q8 ^ (h & 7)) << 4));
        CP_ASYNC16(d, g_wh + g);
    }
}

__global__ __launch_bounds__(GEMM_THREADS, 2) void moe_gemm_kernel(
    const float* __restrict__ eb, float* __restrict__ out)
{
    int pid = blockIdx.y;
    int nhalf = blockIdx.x & 1;
    unsigned tile = blockIdx.x >> 1;
    unsigned cnt = g_pcnt[pid];
    unsigned row0 = tile * 128u;
    if (row0 >= cnt) return;
    int rows = (int)min(128u, cnt - row0);
    int ep = c_pair_p[pid], eq = c_pair_q[pid];

    extern __shared__ char smem[];
    uint32_t sbase = smem_u32(smem);
    unsigned* s_tok = (unsigned*)(smem + OFF_TOK);
    float*    s_gp  = (float*)(smem + OFF_GP);
    float*    s_gq  = (float*)(smem + OFF_GQ);
    float*    s_bp  = (float*)(smem + OFF_BP);
    float*    s_bq  = (float*)(smem + OFF_BQ);

    int tid = threadIdx.x, wid = tid >> 5, lane = tid & 31;

    if (tid < 128) {
        bool v = (tid < rows);
        s_tok[tid] = v ? g_ptok[pid][row0 + tid] : 0u;
        s_gp [tid] = v ? g_pgp[pid][row0 + tid] : 0.f;
        s_gq [tid] = v ? g_pgq[pid][row0 + tid] : 1.f;   // keep ratio finite
    } else {
        int c0 = tid - 128;          // 0..127: bias for this H-half
        s_bp[c0] = eb[ep * HDIM + nhalf * 128 + c0];
        s_bq[c0] = eb[eq * HDIM + nhalf * 128 + c0];
    }
    __syncthreads();

    // A resident (one shot) + 2-stage B pipeline
    load_A_all(sbase, s_tok);
    load_B(sbase, 0, 0, ep, nhalf); CP_COMMIT();   // G0 = A + B0
    load_B(sbase, 1, 1, ep, nhalf); CP_COMMIT();   // G1 = B1

    // warp tile: 4 (M) x 2 (N) -> 32 rows x 64 cols per warp
    int warp_m = wid & 3;
    int warp_n = wid >> 2;

    // ldmatrix lane address components (PTX fragment layouts)
    int laneA_row = (lane & 7) + (((lane >> 3) & 1) << 3);
    int laneA_q   = (lane >> 4) & 1;
    int laneB_n   = (lane & 7) + (((lane >> 4) & 1) << 3);
    int laneB_q   = (lane >> 3) & 1;
    int grp = lane >> 2, tig = lane & 3;

    float acc[2][8][4];
#pragma unroll
    for (int a = 0; a < 2; a++)
#pragma unroll
        for (int b = 0; b < 8; b++)
#pragma unroll
            for (int d = 0; d < 4; d++) acc[a][b][d] = 0.f;

#pragma unroll 1
    for (int c = 0; c < 8; c++) {
        int buf = c & 1;
        if (c == 7) { CP_WAIT(0); } else { CP_WAIT(1); }
        __syncthreads();

        uint32_t aBase = sbase + OFF_A + (c & 3) * 16384;
        uint32_t bBase = sbase + OFF_B + buf * 16384;

#pragma unroll
        for (int ks = 0; ks < 4; ks++) {
            uint32_t ahf[2][4];
#pragma unroll
            for (int mf = 0; mf < 2; mf++) {
                int r = warp_m * 32 + mf * 16 + laneA_row;
                int q8 = ks * 2 + laneA_q;
                uint32_t off = (uint32_t)(r * 128 + ((q8 ^ (r & 7)) << 4));
                ldsm4(aBase + off, ahf[mf]);
            }
#pragma unroll
            for (int nf = 0; nf < 4; nf++) {
                int n = warp_n * 64 + nf * 16 + laneB_n;
                int q8 = ks * 2 + laneB_q;
                uint32_t off = (uint32_t)(n * 128 + ((q8 ^ (n & 7)) << 4));
                uint32_t bh[4];
                ldsm4(bBase + off, bh);
#pragma unroll
                for (int mf = 0; mf < 2; mf++) {
                    mma16816(acc[mf][2 * nf],     ahf[mf], bh[0], bh[1]);
                    mma16816(acc[mf][2 * nf + 1], ahf[mf], bh[2], bh[3]);
                }
            }
        }

        // Between the two expert sweeps: acc *= g_p/g_q per row
        if (c == 3) {
#pragma unroll
            for (int mf = 0; mf < 2; mf++) {
#pragma unroll
                for (int half = 0; half < 2; half++) {
                    int r = warp_m * 32 + mf * 16 + grp + half * 8;
                    float f = s_gp[r] / s_gq[r];
#pragma unroll
                    for (int nf = 0; nf < 8; nf++) {
                        acc[mf][nf][half * 2 + 0] *= f;
                        acc[mf][nf][half * 2 + 1] *= f;
                    }
                }
            }
        }

        __syncthreads();
        if (c < 6) {
            int nc = c + 2;
            load_B(sbase, buf, nc & 3, (nc < 4) ? ep : eq, nhalf);
            CP_COMMIT();
        }
    }

    // Epilogue: out[tok, nhalf-half] = g_q*acc + g_p*b_p + g_q*b_q
#pragma unroll
    for (int mf = 0; mf < 2; mf++) {
#pragma unroll
        for (int half = 0; half < 2; half++) {
            int r = warp_m * 32 + mf * 16 + grp + half * 8;
            if (r < rows) {
                unsigned tok = s_tok[r];
                float gq = s_gq[r], gp = s_gp[r];
                float* dst = out + (size_t)tok * HDIM + nhalf * 128;
#pragma unroll
                for (int nf = 0; nf < 8; nf++) {
                    int col = warp_n * 64 + nf * 8 + tig * 2;
                    float2 v;
                    v.x = gq * acc[mf][nf][half * 2 + 0] + gp * s_bp[col]     + gq * s_bq[col];
                    v.y = gq * acc[mf][nf][half * 2 + 1] + gp * s_bp[col + 1] + gq * s_bq[col + 1];
                    *(float2*)(dst + col) = v;
                }
            }
        }
    }
}

// ============================================================
// Launch
// ============================================================
extern "C" void kernel_launch(void* const* d_in, const int* in_sizes, int n_in,
                              void* d_out, int out_size)
{
    const float* x  = (const float*)d_in[0];
    const float* gw = (const float*)d_in[1];
    const float* gb = (const float*)d_in[2];
    const float* ew = (const float*)d_in[3];
    const float* eb = (const float*)d_in[4];
    float* out = (float*)d_out;

    cudaFuncSetAttribute(moe_gemm_kernel,
                         cudaFuncAttributeMaxDynamicSharedMemorySize, SMEM_TOTAL);

    reset_kernel<<<1, 32>>>();
    convert_w_kernel<<<(NEXP * HDIM * DDIM / 2) / 256, 256>>>(ew);
    gate_route_kernel<<<N_TOK / 8, 256>>>(x, gw, gb);
    moe_gemm_kernel<<<dim3(MAX_TILES * 2, NPAIR), GEMM_THREADS, SMEM_TOTAL>>>(eb, out);
}

// round 15
// speedup vs baseline: 1.1108x; 1.0251x over previous
#include <cuda_runtime.h>
#include <cuda_fp16.h>
#include <cstdint>

// ============================================================
// Problem constants
// ============================================================
#define N_TOK  262144
#define DDIM   256
#define HDIM   256
#define NEXP   8
#define NPAIR  28

// ============================================================
// Device scratch (allocation-free contract: __device__ globals)
// ============================================================
__device__ unsigned g_pcnt[NPAIR];
__device__ unsigned g_ptok[NPAIR][N_TOK];   // token id per routed row
__device__ float    g_pgp [NPAIR][N_TOK];   // gate of lower-index expert p
__device__ float    g_pgq [NPAIR][N_TOK];   // gate of higher-index expert q
__device__ __half   g_xh[(size_t)N_TOK * DDIM];      // x in fp16
__device__ __half   g_wh[NEXP * HDIM * DDIM];        // W in fp16

// pair id -> expert indices
__device__ const int c_pair_p[NPAIR] =
    {0,0,0,0,0,0,0, 1,1,1,1,1,1, 2,2,2,2,2, 3,3,3,3, 4,4,4, 5,5, 6};
__device__ const int c_pair_q[NPAIR] =
    {1,2,3,4,5,6,7, 2,3,4,5,6,7, 3,4,5,6,7, 4,5,6,7, 5,6,7, 6,7, 7};

// ============================================================
// PTX helpers (plain sm_100 ONLY: cp.async, ldmatrix, mma.sync)
// ============================================================
__device__ __forceinline__ uint32_t smem_u32(const void* p) {
    uint32_t a;
    asm("{ .reg .u64 t; cvta.to.shared.u64 t, %1; cvt.u32.u64 %0, t; }" : "=r"(a) : "l"(p));
    return a;
}

#define CP_ASYNC16(dst, src) \
    asm volatile("cp.async.cg.shared.global [%0], [%1], 16;" :: "r"(dst), "l"(src))
#define CP_COMMIT() asm volatile("cp.async.commit_group;" ::: "memory")
#define CP_WAIT(n)  asm volatile("cp.async.wait_group %0;" :: "n"(n) : "memory")
#define NAMED_BAR(id, cnt) \
    asm volatile("bar.sync %0, %1;" :: "r"(id), "r"(cnt) : "memory")

__device__ __forceinline__ void ldsm4(uint32_t addr, uint32_t* r) {
    asm volatile("ldmatrix.sync.aligned.m8n8.x4.shared.b16 {%0,%1,%2,%3}, [%4];"
                 : "=r"(r[0]), "=r"(r[1]), "=r"(r[2]), "=r"(r[3]) : "r"(addr));
}

__device__ __forceinline__ void mma16816(float* c, const uint32_t* a,
                                         uint32_t b0, uint32_t b1) {
    asm volatile(
        "mma.sync.aligned.m16n8k16.row.col.f32.f16.f16.f32 "
        "{%0,%1,%2,%3}, {%4,%5,%6,%7}, {%8,%9}, {%0,%1,%2,%3};"
        : "+f"(c[0]), "+f"(c[1]), "+f"(c[2]), "+f"(c[3])
        : "r"(a[0]), "r"(a[1]), "r"(a[2]), "r"(a[3]), "r"(b0), "r"(b1));
}

// ============================================================
// Kernel 0: reset routing counters (graph-replay safe)
// ============================================================
__global__ void reset_kernel() {
    if (threadIdx.x < NPAIR) g_pcnt[threadIdx.x] = 0u;
}

// ============================================================
// Kernel 1: expert weights fp32 -> fp16
// ============================================================
__global__ void convert_w_kernel(const float* __restrict__ ew) {
    int i = blockIdx.x * 256 + threadIdx.x;           // pair index, total E*H*D/2
    float2 v = ((const float2*)ew)[i];
    __half2 h;
    h.x = __float2half_rn(v.x);
    h.y = __float2half_rn(v.y);
    ((__half2*)g_wh)[i] = h;
}

// ============================================================
// Kernel 2: gate + softmax + top-2 + pair routing + x -> fp16
//   one warp per token, 8 warps per block  (R12 version — measured)
// ============================================================
__global__ __launch_bounds__(256) void gate_route_kernel(
    const float* __restrict__ x,
    const float* __restrict__ gw,
    const float* __restrict__ gb)
{
    __shared__ float sgw[NEXP * DDIM];   // 8KB, 16B-aligned
    __shared__ float sgb[NEXP];
    for (int i = threadIdx.x; i < NEXP * DDIM; i += 256) sgw[i] = gw[i];
    if (threadIdx.x < NEXP) sgb[threadIdx.x] = gb[threadIdx.x];
    __syncthreads();
    const float4* sgw4 = (const float4*)sgw;

    int warp = threadIdx.x >> 5, lane = threadIdx.x & 31;
    int t = blockIdx.x * 8 + warp;

    // two contiguous float4 per lane: cols [lane*4, lane*4+4) and +128
    const float4* xrow4 = (const float4*)(x + (size_t)t * DDIM);
    float4 xv[2];
#pragma unroll
    for (int j = 0; j < 2; j++) xv[j] = xrow4[j * 32 + lane];

    // x -> fp16 (uint2 = 4 halves per store, coalesced)
    uint2* xh4 = (uint2*)(g_xh + (size_t)t * DDIM);
#pragma unroll
    for (int j = 0; j < 2; j++) {
        __half2 lo2, hi2;
        lo2.x = __float2half_rn(xv[j].x);
        lo2.y = __float2half_rn(xv[j].y);
        hi2.x = __float2half_rn(xv[j].z);
        hi2.y = __float2half_rn(xv[j].w);
        uint2 u;
        u.x = *(uint32_t*)&lo2;
        u.y = *(uint32_t*)&hi2;
        xh4[j * 32 + lane] = u;
    }

    // logits (fp32): per expert, 2 LDS.128 of gw + 8 FMA, then 5-level shuffle
    float logit[NEXP];
#pragma unroll
    for (int e = 0; e < NEXP; e++) {
        float a = 0.f;
#pragma unroll
        for (int j = 0; j < 2; j++) {
            float4 w = sgw4[e * 64 + j * 32 + lane];
            a += xv[j].x * w.x + xv[j].y * w.y + xv[j].z * w.z + xv[j].w * w.w;
        }
#pragma unroll
        for (int o = 16; o; o >>= 1) a += __shfl_xor_sync(0xffffffffu, a, o);
        logit[e] = a + sgb[e];
    }

    // top-2 by logit (monotone with softmax prob; ties -> lowest index)
    int i0 = 0; float b0 = logit[0];
#pragma unroll
    for (int e = 1; e < NEXP; e++) if (logit[e] > b0) { b0 = logit[e]; i0 = e; }
    int i1 = -1; float b1 = -3.4e38f;
#pragma unroll
    for (int e = 0; e < NEXP; e++) if (e != i0 && logit[e] > b1) { b1 = logit[e]; i1 = e; }

    // softmax values for the two winners
    float s = 0.f;
#pragma unroll
    for (int e = 0; e < NEXP; e++) s += expf(logit[e] - b0);
    float inv = 1.f / s;
    float gv0 = expf(logit[i0] - b0) * inv;
    float gv1 = expf(logit[i1] - b0) * inv;

    if (lane == 0) {
        int p = min(i0, i1), q = max(i0, i1);
        float gp = (p == i0) ? gv0 : gv1;
        float gq = (p == i0) ? gv1 : gv0;
        int pid = p * 7 - (p * (p - 1)) / 2 + (q - p - 1);
        unsigned pos = atomicAdd(&g_pcnt[pid], 1u);
        g_ptok[pid][pos] = (unsigned)t;
        g_pgp [pid][pos] = gp;
        g_pgq [pid][pos] = gq;
    }
}

// ============================================================
// Kernel 3: pair-fused routed GEMM, single-term fp16 mma.sync
//   block = 128 tokens x ONE 128-col H-half of expert pair (p,q)
//   A (128x256 fp16 = 64 KB) RESIDENT in smem, loaded once.
//   B split into 4 STRIPES of 32 H-cols; each stripe is consumed by
//   one warp PAIR (warp_m 0/1, same warp_n) and double-buffered
//   privately (4 KB x 2). The pair co-loads its own stripe and syncs
//   only via a 64-wide named barrier -> the 4 pairs pipeline
//   independently; no block-wide sync in the mainloop (chunk 0 only,
//   to publish A).
//   8 B-chunks (BK=64): 0-3 sweep W_p, 4-7 sweep W_q; accumulators
//   rescaled by g_p/g_q between sweeps; epilogue direct to out.
//   8 warps (256 thr) in 2(M)x4(N), warp tile 64x32, 2 CTAs/SM.
// ============================================================
static constexpr int OFF_TOK  = 0;      // 128 u32
static constexpr int OFF_GP   = 512;    // 128 f32
static constexpr int OFF_GQ   = 1024;   // 128 f32
static constexpr int OFF_BP   = 1536;   // 128 f32 (this half)
static constexpr int OFF_BQ   = 2048;   // 128 f32 (this half)
static constexpr int OFF_A    = 4096;   // 4 kslices x 16KB = 64 KB resident
static constexpr int OFF_B    = 69632;  // 4 stripes x 2 bufs x 4KB = 32 KB
static constexpr int SMEM_TOTAL = 102400;
#define GEMM_THREADS 256
#define MAX_TILES 256                    // 256*128 = 32768 tokens/pair cap

__device__ __forceinline__ void load_A_all(uint32_t sbase, const unsigned* s_tok)
{
    int tid = threadIdx.x;
    uint32_t a_s = sbase + OFF_A;
    // 128 rows x 256B (4 kslices x 128B) = 4096 16B units
#pragma unroll
    for (int i = 0; i < 16; i++) {
        int u = tid + i * GEMM_THREADS;
        int ks = u >> 10;
        int rem = u & 1023;
        int r = rem >> 3, q8 = rem & 7;
        unsigned tok = s_tok[r];
        size_t g = (size_t)tok * DDIM + ks * 64 + q8 * 8;
        uint32_t d = a_s + (uint32_t)(ks * 16384 + r * 128 + ((q8 ^ (r & 7)) << 4));
        CP_ASYNC16(d, g_xh + g);
    }
}

// pair-cooperative stripe load: 64 lanes load 32 B-rows x 128B = 256 units
__device__ __forceinline__ void load_B_stripe(uint32_t sbase, int warp_n, int buf,
                                              int kslice, int e, int nhalf,
                                              int pair_lane)
{
    uint32_t b_s = sbase + OFF_B + warp_n * 8192 + buf * 4096;
#pragma unroll
    for (int i = 0; i < 4; i++) {
        int v = pair_lane + i * 64;        // 0..255
        int rl = v >> 3, q8 = v & 7;       // local row 0..31
        int h = warp_n * 32 + rl;
        size_t g = (size_t)e * (HDIM * DDIM) + (size_t)(nhalf * 128 + h) * DDIM
                 + kslice * 64 + q8 * 8;
        uint32_t d = b_s + (uint32_t)(rl * 128 + ((q8 ^ (rl & 7)) << 4));
        CP_ASYNC16(d, g_wh + g);
    }
}

__global__ __launch_bounds__(GEMM_THREADS, 2) void moe_gemm_kernel(
    const float* __restrict__ eb, float* __restrict__ out)
{
    int pid = blockIdx.y;
    int nhalf = blockIdx.x & 1;
    unsigned tile = blockIdx.x >> 1;
    unsigned cnt = g_pcnt[pid];
    unsigned row0 = tile * 128u;
    if (row0 >= cnt) return;
    int rows = (int)min(128u, cnt - row0);
    int ep = c_pair_p[pid], eq = c_pair_q[pid];

    extern __shared__ char smem[];
    uint32_t sbase = smem_u32(smem);
    unsigned* s_tok = (unsigned*)(smem + OFF_TOK);
    float*    s_gp  = (float*)(smem + OFF_GP);
    float*    s_gq  = (float*)(smem + OFF_GQ);
    float*    s_bp  = (float*)(smem + OFF_BP);
    float*    s_bq  = (float*)(smem + OFF_BQ);

    int tid = threadIdx.x, wid = tid >> 5, lane = tid & 31;

    if (tid < 128) {
        bool v = (tid < rows);
        s_tok[tid] = v ? g_ptok[pid][row0 + tid] : 0u;
        s_gp [tid] = v ? g_pgp[pid][row0 + tid] : 0.f;
        s_gq [tid] = v ? g_pgq[pid][row0 + tid] : 1.f;   // keep ratio finite
    } else {
        int c0 = tid - 128;          // 0..127: bias for this H-half
        s_bp[c0] = eb[ep * HDIM + nhalf * 128 + c0];
        s_bq[c0] = eb[eq * HDIM + nhalf * 128 + c0];
    }
    __syncthreads();

    // warp tile: 2 (M) x 4 (N) -> 64 rows x 32 cols per warp
    int warp_m = wid & 1;
    int warp_n = wid >> 1;
    int pair_lane = warp_m * 32 + lane;   // 0..63 within the pair
    int barid = 1 + warp_n;

    // A resident (one shot) + per-pair 2-stage B stripe pipeline
    load_A_all(sbase, s_tok);
    load_B_stripe(sbase, warp_n, 0, 0, ep, nhalf, pair_lane); CP_COMMIT(); // G0 = A + B0
    load_B_stripe(sbase, warp_n, 1, 1, ep, nhalf, pair_lane); CP_COMMIT(); // G1 = B1

    // ldmatrix lane address components (PTX fragment layouts)
    int laneA_row = (lane & 7) + (((lane >> 3) & 1) << 3);
    int laneA_q   = (lane >> 4) & 1;
    int laneB_n   = (lane & 7) + (((lane >> 4) & 1) << 3);
    int laneB_q   = (lane >> 3) & 1;
    int grp = lane >> 2, tig = lane & 3;

    float acc[4][4][4];
#pragma unroll
    for (int a = 0; a < 4; a++)
#pragma unroll
        for (int b = 0; b < 4; b++)
#pragma unroll
            for (int d = 0; d < 4; d++) acc[a][b][d] = 0.f;

#pragma unroll 1
    for (int c = 0; c < 8; c++) {
        int buf = c & 1;
        if (c == 7) { CP_WAIT(0); } else { CP_WAIT(1); }
        if (c == 0) { __syncthreads(); }            // publish shared A (+B0)
        else        { NAMED_BAR(barid, 64); }       // publish pair stripe B_c

        uint32_t aBase = sbase + OFF_A + (c & 3) * 16384;
        uint32_t bBase = sbase + OFF_B + warp_n * 8192 + buf * 4096;

#pragma unroll
        for (int ks = 0; ks < 4; ks++) {
            uint32_t ahf[4][4];
#pragma unroll
            for (int mf = 0; mf < 4; mf++) {
                int r = warp_m * 64 + mf * 16 + laneA_row;
                int q8 = ks * 2 + laneA_q;
                uint32_t off = (uint32_t)(r * 128 + ((q8 ^ (r & 7)) << 4));
                ldsm4(aBase + off, ahf[mf]);
            }
#pragma unroll
            for (int nf16 = 0; nf16 < 2; nf16++) {
                int nl = nf16 * 16 + laneB_n;       // local col 0..31
                int q8 = ks * 2 + laneB_q;
                uint32_t off = (uint32_t)(nl * 128 + ((q8 ^ (nl & 7)) << 4));
                uint32_t bh[4];
                ldsm4(bBase + off, bh);
#pragma unroll
                for (int mf = 0; mf < 4; mf++) {
                    mma16816(acc[mf][2 * nf16],     ahf[mf], bh[0], bh[1]);
                    mma16816(acc[mf][2 * nf16 + 1], ahf[mf], bh[2], bh[3]);
                }
            }
        }

        // Between the two expert sweeps: acc *= g_p/g_q per row
        if (c == 3) {
#pragma unroll
            for (int mf = 0; mf < 4; mf++) {
#pragma unroll
                for (int half = 0; half < 2; half++) {
                    int r = warp_m * 64 + mf * 16 + grp + half * 8;
                    float f = s_gp[r] / s_gq[r];
#pragma unroll
                    for (int nf = 0; nf < 4; nf++) {
                        acc[mf][nf][half * 2 + 0] *= f;
                        acc[mf][nf][half * 2 + 1] *= f;
                    }
                }
            }
        }

        if (c < 6) {
            NAMED_BAR(barid, 64);                   // pair done with buf -> safe to overwrite
            int nc = c + 2;
            load_B_stripe(sbase, warp_n, buf, nc & 3, (nc < 4) ? ep : eq,
                          nhalf, pair_lane);
            CP_COMMIT();
        }
    }

    // Epilogue: out[tok, nhalf-half] = g_q*acc + g_p*b_p + g_q*b_q
#pragma unroll
    for (int mf = 0; mf < 4; mf++) {
#pragma unroll
        for (int half = 0; half < 2; half++) {
            int r = warp_m * 64 + mf * 16 + grp + half * 8;
            if (r < rows) {
                unsigned tok = s_tok[r];
                float gq = s_gq[r], gp = s_gp[r];
                float* dst = out + (size_t)tok * HDIM + nhalf * 128;
#pragma unroll
                for (int nf = 0; nf < 4; nf++) {
                    int col = warp_n * 32 + nf * 8 + tig * 2;
                    float2 v;
                    v.x = gq * acc[mf][nf][half * 2 + 0] + gp * s_bp[col]     + gq * s_bq[col];
                    v.y = gq * acc[mf][nf][half * 2 + 1] + gp * s_bp[col + 1] + gq * s_bq[col + 1];
                    *(float2*)(dst + col) = v;
                }
            }
        }
    }
}

// ============================================================
// Launch
// ============================================================
extern "C" void kernel_launch(void* const* d_in, const int* in_sizes, int n_in,
                              void* d_out, int out_size)
{
    const float* x  = (const float*)d_in[0];
    const float* gw = (const float*)d_in[1];
    const float* gb = (const float*)d_in[2];
    const float* ew = (const float*)d_in[3];
    const float* eb = (const float*)d_in[4];
    float* out = (float*)d_out;

    cudaFuncSetAttribute(moe_gemm_kernel,
                         cudaFuncAttributeMaxDynamicSharedMemorySize, SMEM_TOTAL);

    reset_kernel<<<1, 32>>>();
    convert_w_kernel<<<(NEXP * HDIM * DDIM / 2) / 256, 256>>>(ew);
    gate_route_kernel<<<N_TOK / 8, 256>>>(x, gw, gb);
    moe_gemm_kernel<<<dim3(MAX_TILES * 2, NPAIR), GEMM_THREADS, SMEM_TOTAL>>>(eb, out);
}

// round 16
// speedup vs baseline: 1.2495x; 1.1249x over previous
#include <cuda_runtime.h>
#include <cuda_fp16.h>
#include <cstdint>

// ============================================================
// Problem constants
// ============================================================
#define N_TOK  262144
#define DDIM   256
#define HDIM   256
#define NEXP   8
#define NPAIR  28

// ============================================================
// Device scratch (allocation-free contract: __device__ globals)
// ============================================================
__device__ unsigned g_pcnt[NPAIR];
__device__ unsigned g_ptok[NPAIR][N_TOK];   // token id per routed row
__device__ float    g_pgp [NPAIR][N_TOK];   // gate of lower-index expert p
__device__ float    g_pgq [NPAIR][N_TOK];   // gate of higher-index expert q
__device__ __half   g_xh[(size_t)N_TOK * DDIM];      // x in fp16
__device__ __half   g_wh[NEXP * HDIM * DDIM];        // W in fp16

// pair id -> expert indices
__device__ const int c_pair_p[NPAIR] =
    {0,0,0,0,0,0,0, 1,1,1,1,1,1, 2,2,2,2,2, 3,3,3,3, 4,4,4, 5,5, 6};
__device__ const int c_pair_q[NPAIR] =
    {1,2,3,4,5,6,7, 2,3,4,5,6,7, 3,4,5,6,7, 4,5,6,7, 5,6,7, 6,7, 7};

// ============================================================
// PTX helpers (plain sm_100 ONLY: cp.async, ldmatrix, mma.sync)
// ============================================================
__device__ __forceinline__ uint32_t smem_u32(const void* p) {
    uint32_t a;
    asm("{ .reg .u64 t; cvta.to.shared.u64 t, %1; cvt.u32.u64 %0, t; }" : "=r"(a) : "l"(p));
    return a;
}

#define CP_ASYNC16(dst, src) \
    asm volatile("cp.async.cg.shared.global [%0], [%1], 16;" :: "r"(dst), "l"(src))
#define CP_COMMIT() asm volatile("cp.async.commit_group;" ::: "memory")
#define CP_WAIT(n)  asm volatile("cp.async.wait_group %0;" :: "n"(n) : "memory")
#define NAMED_BAR(id, cnt) \
    asm volatile("bar.sync %0, %1;" :: "r"(id), "r"(cnt) : "memory")

__device__ __forceinline__ void ldsm4(uint32_t addr, uint32_t* r) {
    asm volatile("ldmatrix.sync.aligned.m8n8.x4.shared.b16 {%0,%1,%2,%3}, [%4];"
                 : "=r"(r[0]), "=r"(r[1]), "=r"(r[2]), "=r"(r[3]) : "r"(addr));
}

__device__ __forceinline__ void mma16816(float* c, const uint32_t* a,
                                         uint32_t b0, uint32_t b1) {
    asm volatile(
        "mma.sync.aligned.m16n8k16.row.col.f32.f16.f16.f32 "
        "{%0,%1,%2,%3}, {%4,%5,%6,%7}, {%8,%9}, {%0,%1,%2,%3};"
        : "+f"(c[0]), "+f"(c[1]), "+f"(c[2]), "+f"(c[3])
        : "r"(a[0]), "r"(a[1]), "r"(a[2]), "r"(a[3]), "r"(b0), "r"(b1));
}

// ============================================================
// Kernel 0: reset routing counters (graph-replay safe)
// ============================================================
__global__ void reset_kernel() {
    if (threadIdx.x < NPAIR) g_pcnt[threadIdx.x] = 0u;
}

// ============================================================
// Kernel 1: expert weights fp32 -> fp16
// ============================================================
__global__ void convert_w_kernel(const float* __restrict__ ew) {
    int i = blockIdx.x * 256 + threadIdx.x;           // pair index, total E*H*D/2
    float2 v = ((const float2*)ew)[i];
    __half2 h;
    h.x = __float2half_rn(v.x);
    h.y = __float2half_rn(v.y);
    ((__half2*)g_wh)[i] = h;
}

// ============================================================
// Kernel 2: gate + softmax + top-2 + pair routing + x -> fp16
//   block = 64 tokens (8 warps x 8 tokens each, per-token compute
//   identical to the measured R12/R14 version).
//   Routing: winners staged in smem, bin counts via smem atomics,
//   <=28 GLOBAL atomicAdds per block (vs 128) reserve ranges, then
//   64 threads scatter entries. 4.6x fewer global atomics.
// ============================================================
__global__ __launch_bounds__(256) void gate_route_kernel(
    const float* __restrict__ x,
    const float* __restrict__ gw,
    const float* __restrict__ gb)
{
    __shared__ float sgw[NEXP * DDIM];   // 8KB, 16B-aligned
    __shared__ float sgb[NEXP];
    __shared__ unsigned char s_pid[64];
    __shared__ float    s_gpv[64];
    __shared__ float    s_gqv[64];
    __shared__ unsigned s_off[64];
    __shared__ unsigned s_bincnt[NPAIR];
    __shared__ unsigned s_binbase[NPAIR];

    for (int i = threadIdx.x; i < NEXP * DDIM; i += 256) sgw[i] = gw[i];
    if (threadIdx.x < NEXP)  sgb[threadIdx.x] = gb[threadIdx.x];
    if (threadIdx.x < NPAIR) s_bincnt[threadIdx.x] = 0u;
    __syncthreads();
    const float4* sgw4 = (const float4*)sgw;

    int warp = threadIdx.x >> 5, lane = threadIdx.x & 31;
    int t0 = blockIdx.x * 64 + warp * 8;

#pragma unroll 1
    for (int it = 0; it < 8; it++) {
        int t = t0 + it;

        // two contiguous float4 per lane: cols [lane*4,+4) and +128
        const float4* xrow4 = (const float4*)(x + (size_t)t * DDIM);
        float4 xv[2];
#pragma unroll
        for (int j = 0; j < 2; j++) xv[j] = xrow4[j * 32 + lane];

        // x -> fp16 (uint2 = 4 halves per store, coalesced)
        uint2* xh4 = (uint2*)(g_xh + (size_t)t * DDIM);
#pragma unroll
        for (int j = 0; j < 2; j++) {
            __half2 lo2, hi2;
            lo2.x = __float2half_rn(xv[j].x);
            lo2.y = __float2half_rn(xv[j].y);
            hi2.x = __float2half_rn(xv[j].z);
            hi2.y = __float2half_rn(xv[j].w);
            uint2 u;
            u.x = *(uint32_t*)&lo2;
            u.y = *(uint32_t*)&hi2;
            xh4[j * 32 + lane] = u;
        }

        // logits (fp32)
        float logit[NEXP];
#pragma unroll
        for (int e = 0; e < NEXP; e++) {
            float a = 0.f;
#pragma unroll
            for (int j = 0; j < 2; j++) {
                float4 w = sgw4[e * 64 + j * 32 + lane];
                a += xv[j].x * w.x + xv[j].y * w.y + xv[j].z * w.z + xv[j].w * w.w;
            }
#pragma unroll
            for (int o = 16; o; o >>= 1) a += __shfl_xor_sync(0xffffffffu, a, o);
            logit[e] = a + sgb[e];
        }

        // top-2 by logit
        int i0 = 0; float b0 = logit[0];
#pragma unroll
        for (int e = 1; e < NEXP; e++) if (logit[e] > b0) { b0 = logit[e]; i0 = e; }
        int i1 = -1; float b1 = -3.4e38f;
#pragma unroll
        for (int e = 0; e < NEXP; e++) if (e != i0 && logit[e] > b1) { b1 = logit[e]; i1 = e; }

        // softmax values for the two winners
        float s = 0.f;
#pragma unroll
        for (int e = 0; e < NEXP; e++) s += expf(logit[e] - b0);
        float inv = 1.f / s;
        float gv0 = expf(logit[i0] - b0) * inv;
        float gv1 = expf(logit[i1] - b0) * inv;

        if (lane == 0) {
            int p = min(i0, i1), q = max(i0, i1);
            float gp = (p == i0) ? gv0 : gv1;
            float gq = (p == i0) ? gv1 : gv0;
            int pid = p * 7 - (p * (p - 1)) / 2 + (q - p - 1);
            int slot = warp * 8 + it;
            s_pid[slot] = (unsigned char)pid;
            s_gpv[slot] = gp;
            s_gqv[slot] = gq;
            s_off[slot] = atomicAdd(&s_bincnt[pid], 1u);
        }
    }
    __syncthreads();

    // reserve global ranges: <=28 atomics per block
    if (threadIdx.x < NPAIR) {
        unsigned c = s_bincnt[threadIdx.x];
        s_binbase[threadIdx.x] = c ? atomicAdd(&g_pcnt[threadIdx.x], c) : 0u;
    }
    __syncthreads();

    // scatter the 64 entries
    if (threadIdx.x < 64) {
        int pid = s_pid[threadIdx.x];
        unsigned pos = s_binbase[pid] + s_off[threadIdx.x];
        g_ptok[pid][pos] = (unsigned)(blockIdx.x * 64 + threadIdx.x);
        g_pgp [pid][pos] = s_gpv[threadIdx.x];
        g_pgq [pid][pos] = s_gqv[threadIdx.x];
    }
}

// ============================================================
// Kernel 3: pair-fused routed GEMM, single-term fp16 mma.sync
//   (R15 version — measured 239.6us; byte-identical)
//   block = 128 tokens x ONE 128-col H-half of expert pair (p,q)
//   A resident (64 KB); B in 4 per-pair stripes, double-buffered,
//   64-wide named barriers; 8 warps 2(M)x4(N), 2 CTAs/SM.
// ============================================================
static constexpr int OFF_TOK  = 0;      // 128 u32
static constexpr int OFF_GP   = 512;    // 128 f32
static constexpr int OFF_GQ   = 1024;   // 128 f32
static constexpr int OFF_BP   = 1536;   // 128 f32 (this half)
static constexpr int OFF_BQ   = 2048;   // 128 f32 (this half)
static constexpr int OFF_A    = 4096;   // 4 kslices x 16KB = 64 KB resident
static constexpr int OFF_B    = 69632;  // 4 stripes x 2 bufs x 4KB = 32 KB
static constexpr int SMEM_TOTAL = 102400;
#define GEMM_THREADS 256
#define MAX_TILES 256                    // 256*128 = 32768 tokens/pair cap

__device__ __forceinline__ void load_A_all(uint32_t sbase, const unsigned* s_tok)
{
    int tid = threadIdx.x;
    uint32_t a_s = sbase + OFF_A;
#pragma unroll
    for (int i = 0; i < 16; i++) {
        int u = tid + i * GEMM_THREADS;
        int ks = u >> 10;
        int rem = u & 1023;
        int r = rem >> 3, q8 = rem & 7;
        unsigned tok = s_tok[r];
        size_t g = (size_t)tok * DDIM + ks * 64 + q8 * 8;
        uint32_t d = a_s + (uint32_t)(ks * 16384 + r * 128 + ((q8 ^ (r & 7)) << 4));
        CP_ASYNC16(d, g_xh + g);
    }
}

// pair-cooperative stripe load: 64 lanes load 32 B-rows x 128B = 256 units
__device__ __forceinline__ void load_B_stripe(uint32_t sbase, int warp_n, int buf,
                                              int kslice, int e, int nhalf,
                                              int pair_lane)
{
    uint32_t b_s = sbase + OFF_B + warp_n * 8192 + buf * 4096;
#pragma unroll
    for (int i = 0; i < 4; i++) {
        int v = pair_lane + i * 64;        // 0..255
        int rl = v >> 3, q8 = v & 7;       // local row 0..31
        int h = warp_n * 32 + rl;
        size_t g = (size_t)e * (HDIM * DDIM) + (size_t)(nhalf * 128 + h) * DDIM
                 + kslice * 64 + q8 * 8;
        uint32_t d = b_s + (uint32_t)(rl * 128 + ((q8 ^ (rl & 7)) << 4));
        CP_ASYNC16(d, g_wh + g);
    }
}

__global__ __launch_bounds__(GEMM_THREADS, 2) void moe_gemm_kernel(
    const float* __restrict__ eb, float* __restrict__ out)
{
    int pid = blockIdx.y;
    int nhalf = blockIdx.x & 1;
    unsigned tile = blockIdx.x >> 1;
    unsigned cnt = g_pcnt[pid];
    unsigned row0 = tile * 128u;
    if (row0 >= cnt) return;
    int rows = (int)min(128u, cnt - row0);
    int ep = c_pair_p[pid], eq = c_pair_q[pid];

    extern __shared__ char smem[];
    uint32_t sbase = smem_u32(smem);
    unsigned* s_tok = (unsigned*)(smem + OFF_TOK);
    float*    s_gp  = (float*)(smem + OFF_GP);
    float*    s_gq  = (float*)(smem + OFF_GQ);
    float*    s_bp  = (float*)(smem + OFF_BP);
    float*    s_bq  = (float*)(smem + OFF_BQ);

    int tid = threadIdx.x, wid = tid >> 5, lane = tid & 31;

    if (tid < 128) {
        bool v = (tid < rows);
        s_tok[tid] = v ? g_ptok[pid][row0 + tid] : 0u;
        s_gp [tid] = v ? g_pgp[pid][row0 + tid] : 0.f;
        s_gq [tid] = v ? g_pgq[pid][row0 + tid] : 1.f;   // keep ratio finite
    } else {
        int c0 = tid - 128;          // 0..127: bias for this H-half
        s_bp[c0] = eb[ep * HDIM + nhalf * 128 + c0];
        s_bq[c0] = eb[eq * HDIM + nhalf * 128 + c0];
    }
    __syncthreads();

    // warp tile: 2 (M) x 4 (N) -> 64 rows x 32 cols per warp
    int warp_m = wid & 1;
    int warp_n = wid >> 1;
    int pair_lane = warp_m * 32 + lane;   // 0..63 within the pair
    int barid = 1 + warp_n;

    // A resident (one shot) + per-pair 2-stage B stripe pipeline
    load_A_all(sbase, s_tok);
    load_B_stripe(sbase, warp_n, 0, 0, ep, nhalf, pair_lane); CP_COMMIT(); // G0 = A + B0
    load_B_stripe(sbase, warp_n, 1, 1, ep, nhalf, pair_lane); CP_COMMIT(); // G1 = B1

    // ldmatrix lane address components (PTX fragment layouts)
    int laneA_row = (lane & 7) + (((lane >> 3) & 1) << 3);
    int laneA_q   = (lane >> 4) & 1;
    int laneB_n   = (lane & 7) + (((lane >> 4) & 1) << 3);
    int laneB_q   = (lane >> 3) & 1;
    int grp = lane >> 2, tig = lane & 3;

    float acc[4][4][4];
#pragma unroll
    for (int a = 0; a < 4; a++)
#pragma unroll
        for (int b = 0; b < 4; b++)
#pragma unroll
            for (int d = 0; d < 4; d++) acc[a][b][d] = 0.f;

#pragma unroll 1
    for (int c = 0; c < 8; c++) {
        int buf = c & 1;
        if (c == 7) { CP_WAIT(0); } else { CP_WAIT(1); }
        if (c == 0) { __syncthreads(); }            // publish shared A (+B0)
        else        { NAMED_BAR(barid, 64); }       // publish pair stripe B_c

        uint32_t aBase = sbase + OFF_A + (c & 3) * 16384;
        uint32_t bBase = sbase + OFF_B + warp_n * 8192 + buf * 4096;

#pragma unroll
        for (int ks = 0; ks < 4; ks++) {
            uint32_t ahf[4][4];
#pragma unroll
            for (int mf = 0; mf < 4; mf++) {
                int r = warp_m * 64 + mf * 16 + laneA_row;
                int q8 = ks * 2 + laneA_q;
                uint32_t off = (uint32_t)(r * 128 + ((q8 ^ (r & 7)) << 4));
                ldsm4(aBase + off, ahf[mf]);
            }
#pragma unroll
            for (int nf16 = 0; nf16 < 2; nf16++) {
                int nl = nf16 * 16 + laneB_n;       // local col 0..31
                int q8 = ks * 2 + laneB_q;
                uint32_t off = (uint32_t)(nl * 128 + ((q8 ^ (nl & 7)) << 4));
                uint32_t bh[4];
                ldsm4(bBase + off, bh);
#pragma unroll
                for (int mf = 0; mf < 4; mf++) {
                    mma16816(acc[mf][2 * nf16],     ahf[mf], bh[0], bh[1]);
                    mma16816(acc[mf][2 * nf16 + 1], ahf[mf], bh[2], bh[3]);
                }
            }
        }

        // Between the two expert sweeps: acc *= g_p/g_q per row
        if (c == 3) {
#pragma unroll
            for (int mf = 0; mf < 4; mf++) {
#pragma unroll
                for (int half = 0; half < 2; half++) {
                    int r = warp_m * 64 + mf * 16 + grp + half * 8;
                    float f = s_gp[r] / s_gq[r];
#pragma unroll
                    for (int nf = 0; nf < 4; nf++) {
                        acc[mf][nf][half * 2 + 0] *= f;
                        acc[mf][nf][half * 2 + 1] *= f;
                    }
                }
            }
        }

        if (c < 6) {
            NAMED_BAR(barid, 64);                   // pair done with buf -> safe to overwrite
            int nc = c + 2;
            load_B_stripe(sbase, warp_n, buf, nc & 3, (nc < 4) ? ep : eq,
                          nhalf, pair_lane);
            CP_COMMIT();
        }
    }

    // Epilogue: out[tok, nhalf-half] = g_q*acc + g_p*b_p + g_q*b_q
#pragma unroll
    for (int mf = 0; mf < 4; mf++) {
#pragma unroll
        for (int half = 0; half < 2; half++) {
            int r = warp_m * 64 + mf * 16 + grp + half * 8;
            if (r < rows) {
                unsigned tok = s_tok[r];
                float gq = s_gq[r], gp = s_gp[r];
                float* dst = out + (size_t)tok * HDIM + nhalf * 128;
#pragma unroll
                for (int nf = 0; nf < 4; nf++) {
                    int col = warp_n * 32 + nf * 8 + tig * 2;
                    float2 v;
                    v.x = gq * acc[mf][nf][half * 2 + 0] + gp * s_bp[col]     + gq * s_bq[col];
                    v.y = gq * acc[mf][nf][half * 2 + 1] + gp * s_bp[col + 1] + gq * s_bq[col + 1];
                    *(float2*)(dst + col) = v;
                }
            }
        }
    }
}

// ============================================================
// Launch
// ============================================================
extern "C" void kernel_launch(void* const* d_in, const int* in_sizes, int n_in,
                              void* d_out, int out_size)
{
    const float* x  = (const float*)d_in[0];
    const float* gw = (const float*)d_in[1];
    const float* gb = (const float*)d_in[2];
    const float* ew = (const float*)d_in[3];
    const float* eb = (const float*)d_in[4];
    float* out = (float*)d_out;

    cudaFuncSetAttribute(moe_gemm_kernel,
                         cudaFuncAttributeMaxDynamicSharedMemorySize, SMEM_TOTAL);

    reset_kernel<<<1, 32>>>();
    convert_w_kernel<<<(NEXP * HDIM * DDIM / 2) / 256, 256>>>(ew);
    gate_route_kernel<<<N_TOK / 64, 256>>>(x, gw, gb);
    moe_gemm_kernel<<<dim3(MAX_TILES * 2, NPAIR), GEMM_THREADS, SMEM_TOTAL>>>(eb, out);
}

// round 17
// speedup vs baseline: 1.2540x; 1.0037x over previous
#include <cuda_runtime.h>
#include <cuda_fp16.h>
#include <cstdint>

// ============================================================
// Problem constants
// ============================================================
#define N_TOK  262144
#define DDIM   256
#define HDIM   256
#define NEXP   8
#define NPAIR  28

// ============================================================
// Device scratch (allocation-free contract: __device__ globals)
// ============================================================
__device__ unsigned g_pcnt[NPAIR];
__device__ unsigned g_ptok[NPAIR][N_TOK];   // token id per routed row
__device__ float    g_pgp [NPAIR][N_TOK];   // gate of lower-index expert p
__device__ float    g_pgq [NPAIR][N_TOK];   // gate of higher-index expert q
__device__ __half   g_xh[(size_t)N_TOK * DDIM];      // x in fp16
__device__ __half   g_wh[NEXP * HDIM * DDIM];        // W in fp16

// pair id -> expert indices
__device__ const int c_pair_p[NPAIR] =
    {0,0,0,0,0,0,0, 1,1,1,1,1,1, 2,2,2,2,2, 3,3,3,3, 4,4,4, 5,5, 6};
__device__ const int c_pair_q[NPAIR] =
    {1,2,3,4,5,6,7, 2,3,4,5,6,7, 3,4,5,6,7, 4,5,6,7, 5,6,7, 6,7, 7};

// ============================================================
// PTX helpers (plain sm_100 ONLY: cp.async, ldmatrix, mma.sync)
// ============================================================
__device__ __forceinline__ uint32_t smem_u32(const void* p) {
    uint32_t a;
    asm("{ .reg .u64 t; cvta.to.shared.u64 t, %1; cvt.u32.u64 %0, t; }" : "=r"(a) : "l"(p));
    return a;
}

#define CP_ASYNC16(dst, src) \
    asm volatile("cp.async.cg.shared.global [%0], [%1], 16;" :: "r"(dst), "l"(src))
#define CP_COMMIT() asm volatile("cp.async.commit_group;" ::: "memory")
#define CP_WAIT(n)  asm volatile("cp.async.wait_group %0;" :: "n"(n) : "memory")
#define NAMED_BAR(id, cnt) \
    asm volatile("bar.sync %0, %1;" :: "r"(id), "r"(cnt) : "memory")

__device__ __forceinline__ void ldsm4(uint32_t addr, uint32_t* r) {
    asm volatile("ldmatrix.sync.aligned.m8n8.x4.shared.b16 {%0,%1,%2,%3}, [%4];"
                 : "=r"(r[0]), "=r"(r[1]), "=r"(r[2]), "=r"(r[3]) : "r"(addr));
}

__device__ __forceinline__ void mma16816(float* c, const uint32_t* a,
                                         uint32_t b0, uint32_t b1) {
    asm volatile(
        "mma.sync.aligned.m16n8k16.row.col.f32.f16.f16.f32 "
        "{%0,%1,%2,%3}, {%4,%5,%6,%7}, {%8,%9}, {%0,%1,%2,%3};"
        : "+f"(c[0]), "+f"(c[1]), "+f"(c[2]), "+f"(c[3])
        : "r"(a[0]), "r"(a[1]), "r"(a[2]), "r"(a[3]), "r"(b0), "r"(b1));
}

// ============================================================
// Kernel 0: reset routing counters (graph-replay safe)
// ============================================================
__global__ void reset_kernel() {
    if (threadIdx.x < NPAIR) g_pcnt[threadIdx.x] = 0u;
}

// ============================================================
// Kernel 1: expert weights fp32 -> fp16
// ============================================================
__global__ void convert_w_kernel(const float* __restrict__ ew) {
    int i = blockIdx.x * 256 + threadIdx.x;           // pair index, total E*H*D/2
    float2 v = ((const float2*)ew)[i];
    __half2 h;
    h.x = __float2half_rn(v.x);
    h.y = __float2half_rn(v.y);
    ((__half2*)g_wh)[i] = h;
}

// ============================================================
// Kernel 2: gate + softmax + top-2 + pair routing + x -> fp16
//   block = 64 tokens (8 warps x 8 tokens each).
//   R16 block-aggregated atomics (measured: tail 184 -> 137 us)
//   + NEW: software prefetch of the next token's x (MLP 2 -> 4,
//   load->use distance = one full iteration) to hide DRAM latency.
//   Math order unchanged -> bitwise-identical output.
// ============================================================
__global__ __launch_bounds__(256) void gate_route_kernel(
    const float* __restrict__ x,
    const float* __restrict__ gw,
    const float* __restrict__ gb)
{
    __shared__ float sgw[NEXP * DDIM];   // 8KB, 16B-aligned
    __shared__ float sgb[NEXP];
    __shared__ unsigned char s_pid[64];
    __shared__ float    s_gpv[64];
    __shared__ float    s_gqv[64];
    __shared__ unsigned s_off[64];
    __shared__ unsigned s_bincnt[NPAIR];
    __shared__ unsigned s_binbase[NPAIR];

    for (int i = threadIdx.x; i < NEXP * DDIM; i += 256) sgw[i] = gw[i];
    if (threadIdx.x < NEXP)  sgb[threadIdx.x] = gb[threadIdx.x];
    if (threadIdx.x < NPAIR) s_bincnt[threadIdx.x] = 0u;
    __syncthreads();
    const float4* sgw4 = (const float4*)sgw;

    int warp = threadIdx.x >> 5, lane = threadIdx.x & 31;
    int t0 = blockIdx.x * 64 + warp * 8;

    // prefetch iteration 0
    float4 xv[2];
    {
        const float4* xr = (const float4*)(x + (size_t)t0 * DDIM);
        xv[0] = xr[lane];
        xv[1] = xr[32 + lane];
    }

#pragma unroll 1
    for (int it = 0; it < 8; it++) {
        int t = t0 + it;

        // prefetch next token's x before consuming this one's
        float4 xn[2];
        if (it < 7) {
            const float4* xr = (const float4*)(x + (size_t)(t + 1) * DDIM);
            xn[0] = xr[lane];
            xn[1] = xr[32 + lane];
        }

        // x -> fp16 (uint2 = 4 halves per store, coalesced)
        uint2* xh4 = (uint2*)(g_xh + (size_t)t * DDIM);
#pragma unroll
        for (int j = 0; j < 2; j++) {
            __half2 lo2, hi2;
            lo2.x = __float2half_rn(xv[j].x);
            lo2.y = __float2half_rn(xv[j].y);
            hi2.x = __float2half_rn(xv[j].z);
            hi2.y = __float2half_rn(xv[j].w);
            uint2 u;
            u.x = *(uint32_t*)&lo2;
            u.y = *(uint32_t*)&hi2;
            xh4[j * 32 + lane] = u;
        }

        // logits (fp32)
        float logit[NEXP];
#pragma unroll
        for (int e = 0; e < NEXP; e++) {
            float a = 0.f;
#pragma unroll
            for (int j = 0; j < 2; j++) {
                float4 w = sgw4[e * 64 + j * 32 + lane];
                a += xv[j].x * w.x + xv[j].y * w.y + xv[j].z * w.z + xv[j].w * w.w;
            }
#pragma unroll
            for (int o = 16; o; o >>= 1) a += __shfl_xor_sync(0xffffffffu, a, o);
            logit[e] = a + sgb[e];
        }

        // top-2 by logit
        int i0 = 0; float b0 = logit[0];
#pragma unroll
        for (int e = 1; e < NEXP; e++) if (logit[e] > b0) { b0 = logit[e]; i0 = e; }
        int i1 = -1; float b1 = -3.4e38f;
#pragma unroll
        for (int e = 0; e < NEXP; e++) if (e != i0 && logit[e] > b1) { b1 = logit[e]; i1 = e; }

        // softmax values for the two winners
        float s = 0.f;
#pragma unroll
        for (int e = 0; e < NEXP; e++) s += expf(logit[e] - b0);
        float inv = 1.f / s;
        float gv0 = expf(logit[i0] - b0) * inv;
        float gv1 = expf(logit[i1] - b0) * inv;

        if (lane == 0) {
            int p = min(i0, i1), q = max(i0, i1);
            float gp = (p == i0) ? gv0 : gv1;
            float gq = (p == i0) ? gv1 : gv0;
            int pid = p * 7 - (p * (p - 1)) / 2 + (q - p - 1);
            int slot = warp * 8 + it;
            s_pid[slot] = (unsigned char)pid;
            s_gpv[slot] = gp;
            s_gqv[slot] = gq;
            s_off[slot] = atomicAdd(&s_bincnt[pid], 1u);
        }

        xv[0] = xn[0];
        xv[1] = xn[1];
    }
    __syncthreads();

    // reserve global ranges: <=28 atomics per block
    if (threadIdx.x < NPAIR) {
        unsigned c = s_bincnt[threadIdx.x];
        s_binbase[threadIdx.x] = c ? atomicAdd(&g_pcnt[threadIdx.x], c) : 0u;
    }
    __syncthreads();

    // scatter the 64 entries
    if (threadIdx.x < 64) {
        int pid = s_pid[threadIdx.x];
        unsigned pos = s_binbase[pid] + s_off[threadIdx.x];
        g_ptok[pid][pos] = (unsigned)(blockIdx.x * 64 + threadIdx.x);
        g_pgp [pid][pos] = s_gpv[threadIdx.x];
        g_pgq [pid][pos] = s_gqv[threadIdx.x];
    }
}

// ============================================================
// Kernel 3: pair-fused routed GEMM, single-term fp16 mma.sync
//   (R15/R16 version — measured 239.6us; byte-identical)
//   block = 128 tokens x ONE 128-col H-half of expert pair (p,q)
//   A resident (64 KB); B in 4 per-pair stripes, double-buffered,
//   64-wide named barriers; 8 warps 2(M)x4(N), 2 CTAs/SM.
// ============================================================
static constexpr int OFF_TOK  = 0;      // 128 u32
static constexpr int OFF_GP   = 512;    // 128 f32
static constexpr int OFF_GQ   = 1024;   // 128 f32
static constexpr int OFF_BP   = 1536;   // 128 f32 (this half)
static constexpr int OFF_BQ   = 2048;   // 128 f32 (this half)
static constexpr int OFF_A    = 4096;   // 4 kslices x 16KB = 64 KB resident
static constexpr int OFF_B    = 69632;  // 4 stripes x 2 bufs x 4KB = 32 KB
static constexpr int SMEM_TOTAL = 102400;
#define GEMM_THREADS 256
#define MAX_TILES 256                    // 256*128 = 32768 tokens/pair cap

__device__ __forceinline__ void load_A_all(uint32_t sbase, const unsigned* s_tok)
{
    int tid = threadIdx.x;
    uint32_t a_s = sbase + OFF_A;
#pragma unroll
    for (int i = 0; i < 16; i++) {
        int u = tid + i * GEMM_THREADS;
        int ks = u >> 10;
        int rem = u & 1023;
        int r = rem >> 3, q8 = rem & 7;
        unsigned tok = s_tok[r];
        size_t g = (size_t)tok * DDIM + ks * 64 + q8 * 8;
        uint32_t d = a_s + (uint32_t)(ks * 16384 + r * 128 + ((q8 ^ (r & 7)) << 4));
        CP_ASYNC16(d, g_xh + g);
    }
}

// pair-cooperative stripe load: 64 lanes load 32 B-rows x 128B = 256 units
__device__ __forceinline__ void load_B_stripe(uint32_t sbase, int warp_n, int buf,
                                              int kslice, int e, int nhalf,
                                              int pair_lane)
{
    uint32_t b_s = sbase + OFF_B + warp_n * 8192 + buf * 4096;
#pragma unroll
    for (int i = 0; i < 4; i++) {
        int v = pair_lane + i * 64;        // 0..255
        int rl = v >> 3, q8 = v & 7;       // local row 0..31
        int h = warp_n * 32 + rl;
        size_t g = (size_t)e * (HDIM * DDIM) + (size_t)(nhalf * 128 + h) * DDIM
                 + kslice * 64 + q8 * 8;
        uint32_t d = b_s + (uint32_t)(rl * 128 + ((q8 ^ (rl & 7)) << 4));
        CP_ASYNC16(d, g_wh + g);
    }
}

__global__ __launch_bounds__(GEMM_THREADS, 2) void moe_gemm_kernel(
    const float* __restrict__ eb, float* __restrict__ out)
{
    int pid = blockIdx.y;
    int nhalf = blockIdx.x & 1;
    unsigned tile = blockIdx.x >> 1;
    unsigned cnt = g_pcnt[pid];
    unsigned row0 = tile * 128u;
    if (row0 >= cnt) return;
    int rows = (int)min(128u, cnt - row0);
    int ep = c_pair_p[pid], eq = c_pair_q[pid];

    extern __shared__ char smem[];
    uint32_t sbase = smem_u32(smem);
    unsigned* s_tok = (unsigned*)(smem + OFF_TOK);
    float*    s_gp  = (float*)(smem + OFF_GP);
    float*    s_gq  = (float*)(smem + OFF_GQ);
    float*    s_bp  = (float*)(smem + OFF_BP);
    float*    s_bq  = (float*)(smem + OFF_BQ);

    int tid = threadIdx.x, wid = tid >> 5, lane = tid & 31;

    if (tid < 128) {
        bool v = (tid < rows);
        s_tok[tid] = v ? g_ptok[pid][row0 + tid] : 0u;
        s_gp [tid] = v ? g_pgp[pid][row0 + tid] : 0.f;
        s_gq [tid] = v ? g_pgq[pid][row0 + tid] : 1.f;   // keep ratio finite
    } else {
        int c0 = tid - 128;          // 0..127: bias for this H-half
        s_bp[c0] = eb[ep * HDIM + nhalf * 128 + c0];
        s_bq[c0] = eb[eq * HDIM + nhalf * 128 + c0];
    }
    __syncthreads();

    // warp tile: 2 (M) x 4 (N) -> 64 rows x 32 cols per warp
    int warp_m = wid & 1;
    int warp_n = wid >> 1;
    int pair_lane = warp_m * 32 + lane;   // 0..63 within the pair
    int barid = 1 + warp_n;

    // A resident (one shot) + per-pair 2-stage B stripe pipeline
    load_A_all(sbase, s_tok);
    load_B_stripe(sbase, warp_n, 0, 0, ep, nhalf, pair_lane); CP_COMMIT(); // G0 = A + B0
    load_B_stripe(sbase, warp_n, 1, 1, ep, nhalf, pair_lane); CP_COMMIT(); // G1 = B1

    // ldmatrix lane address components (PTX fragment layouts)
    int laneA_row = (lane & 7) + (((lane >> 3) & 1) << 3);
    int laneA_q   = (lane >> 4) & 1;
    int laneB_n   = (lane & 7) + (((lane >> 4) & 1) << 3);
    int laneB_q   = (lane >> 3) & 1;
    int grp = lane >> 2, tig = lane & 3;

    float acc[4][4][4];
#pragma unroll
    for (int a = 0; a < 4; a++)
#pragma unroll
        for (int b = 0; b < 4; b++)
#pragma unroll
            for (int d = 0; d < 4; d++) acc[a][b][d] = 0.f;

#pragma unroll 1
    for (int c = 0; c < 8; c++) {
        int buf = c & 1;
        if (c == 7) { CP_WAIT(0); } else { CP_WAIT(1); }
        if (c == 0) { __syncthreads(); }            // publish shared A (+B0)
        else        { NAMED_BAR(barid, 64); }       // publish pair stripe B_c

        uint32_t aBase = sbase + OFF_A + (c & 3) * 16384;
        uint32_t bBase = sbase + OFF_B + warp_n * 8192 + buf * 4096;

#pragma unroll
        for (int ks = 0; ks < 4; ks++) {
            uint32_t ahf[4][4];
#pragma unroll
            for (int mf = 0; mf < 4; mf++) {
                int r = warp_m * 64 + mf * 16 + laneA_row;
                int q8 = ks * 2 + laneA_q;
                uint32_t off = (uint32_t)(r * 128 + ((q8 ^ (r & 7)) << 4));
                ldsm4(aBase + off, ahf[mf]);
            }
#pragma unroll
            for (int nf16 = 0; nf16 < 2; nf16++) {
                int nl = nf16 * 16 + laneB_n;       // local col 0..31
                int q8 = ks * 2 + laneB_q;
                uint32_t off = (uint32_t)(nl * 128 + ((q8 ^ (nl & 7)) << 4));
                uint32_t bh[4];
                ldsm4(bBase + off, bh);
#pragma unroll
                for (int mf = 0; mf < 4; mf++) {
                    mma16816(acc[mf][2 * nf16],     ahf[mf], bh[0], bh[1]);
                    mma16816(acc[mf][2 * nf16 + 1], ahf[mf], bh[2], bh[3]);
                }
            }
        }

        // Between the two expert sweeps: acc *= g_p/g_q per row
        if (c == 3) {
#pragma unroll
            for (int mf = 0; mf < 4; mf++) {
#pragma unroll
                for (int half = 0; half < 2; half++) {
                    int r = warp_m * 64 + mf * 16 + grp + half * 8;
                    float f = s_gp[r] / s_gq[r];
#pragma unroll
                    for (int nf = 0; nf < 4; nf++) {
                        acc[mf][nf][half * 2 + 0] *= f;
                        acc[mf][nf][half * 2 + 1] *= f;
                    }
                }
            }
        }

        if (c < 6) {
            NAMED_BAR(barid, 64);                   // pair done with buf -> safe to overwrite
            int nc = c + 2;
            load_B_stripe(sbase, warp_n, buf, nc & 3, (nc < 4) ? ep : eq,
                          nhalf, pair_lane);
            CP_COMMIT();
        }
    }

    // Epilogue: out[tok, nhalf-half] = g_q*acc + g_p*b_p + g_q*b_q
#pragma unroll
    for (int mf = 0; mf < 4; mf++) {
#pragma unroll
        for (int half = 0; half < 2; half++) {
            int r = warp_m * 64 + mf * 16 + grp + half * 8;
            if (r < rows) {
                unsigned tok = s_tok[r];
                float gq = s_gq[r], gp = s_gp[r];
                float* dst = out + (size_t)tok * HDIM + nhalf * 128;
#pragma unroll
                for (int nf = 0; nf < 4; nf++) {
                    int col = warp_n * 32 + nf * 8 + tig * 2;
                    float2 v;
                    v.x = gq * acc[mf][nf][half * 2 + 0] + gp * s_bp[col]     + gq * s_bq[col];
                    v.y = gq * acc[mf][nf][half * 2 + 1] + gp * s_bp[col + 1] + gq * s_bq[col + 1];
                    *(float2*)(dst + col) = v;
                }
            }
        }
    }
}

// ============================================================
// Launch
// ============================================================
extern "C" void kernel_launch(void* const* d_in, const int* in_sizes, int n_in,
                              void* d_out, int out_size)
{
    const float* x  = (const float*)d_in[0];
    const float* gw = (const float*)d_in[1];
    const float* gb = (const float*)d_in[2];
    const float* ew = (const float*)d_in[3];
    const float* eb = (const float*)d_in[4];
    float* out = (float*)d_out;

    cudaFuncSetAttribute(moe_gemm_kernel,
                         cudaFuncAttributeMaxDynamicSharedMemorySize, SMEM_TOTAL);

    reset_kernel<<<1, 32>>>();
    convert_w_kernel<<<(NEXP * HDIM * DDIM / 2) / 256, 256>>>(ew);
    gate_route_kernel<<<N_TOK / 64, 256>>>(x, gw, gb);
    moe_gemm_kernel<<<dim3(MAX_TILES * 2, NPAIR), GEMM_THREADS, SMEM_TOTAL>>>(eb, out);
}